// round 1
// baseline (speedup 1.0000x reference)
#include <cuda_runtime.h>
#include <math.h>

// Problem shape (fixed by the dataset)
#define N_ROWS 4096
#define DIMS   1024
#define NCLS   64

// GEMM tiling
#define BM 128
#define BN 128
#define BK 8
#define SPLITS 8
#define JTILES_PER_SPLIT ((N_ROWS / BN) / SPLITS)   // 4 column tiles per split

#define INV_T 14.285714285714286f   // 1 / 0.07

// ---------------- scratch (device globals; no allocations allowed) ----------
__device__ unsigned long long g_mask[N_ROWS];
__device__ float g_w[N_ROWS];
__device__ float g_bce_part[N_ROWS];
__device__ float g_pm[SPLITS * N_ROWS];
__device__ float g_pp[SPLITS * N_ROWS];
__device__ float g_ps[SPLITS * N_ROWS];

// ---------------- kernel 1: per-row prep (BCE, entropy weights, bitmask) ----
__global__ void prep_kernel(const float* __restrict__ logits,
                            const int* __restrict__ labels) {
    const int row = blockIdx.x;
    const int c = threadIdx.x;            // 0..63
    const int idx = row * NCLS + c;

    const float x = logits[idx];
    const int lab = labels[idx];
    const float y = (float)lab;

    // stable BCE-with-logits term
    float bce = fmaxf(x, 0.f) - x * y + log1pf(expf(-fabsf(x)));

    // entropy weight numerator/denominator
    const float pr = 1.f / (1.f + expf(-x));
    const float ent = -(pr * logf(pr + 1e-8f) + (1.f - pr) * logf(1.f - pr + 1e-8f));
    float wn = ent * y;
    float wd = y;

    const unsigned bal = __ballot_sync(0xffffffffu, lab != 0);

    #pragma unroll
    for (int off = 16; off > 0; off >>= 1) {
        bce += __shfl_down_sync(0xffffffffu, bce, off);
        wn  += __shfl_down_sync(0xffffffffu, wn, off);
        wd  += __shfl_down_sync(0xffffffffu, wd, off);
    }

    __shared__ float sb[2], sn[2], sd[2];
    __shared__ unsigned smk[2];
    const int w = threadIdx.x >> 5;
    if ((threadIdx.x & 31) == 0) { sb[w] = bce; sn[w] = wn; sd[w] = wd; smk[w] = bal; }
    __syncthreads();
    if (threadIdx.x == 0) {
        g_bce_part[row] = sb[0] + sb[1];
        g_w[row] = (sn[0] + sn[1]) / (sd[0] + sd[1] + 1e-8f);
        g_mask[row] = ((unsigned long long)smk[1] << 32) | (unsigned long long)smk[0];
    }
}

// ---------------- kernel 2: fused sim-GEMM + online softmax sums ------------
__global__ __launch_bounds__(256, 2)
void sim_kernel(const float* __restrict__ emb) {
    __shared__ float As[BK][BM];
    __shared__ float Bs[BK][BN];
    __shared__ unsigned long long rmaskS[BM];
    __shared__ unsigned long long cmaskS[BN];

    const int rowBase = blockIdx.x * BM;
    const int split = blockIdx.y;
    const int tid = threadIdx.x;
    const int ty = tid >> 4;              // 0..15 (row group)
    const int tx = tid & 15;              // 0..15 (col group)
    const int lr = tid >> 1;              // 0..127 load row
    const int lh = (tid & 1) * 4;         // 0 or 4 (k offset)

    if (tid < BM) rmaskS[tid] = g_mask[rowBase + tid];

    float m[8], p[8], s[8];
    #pragma unroll
    for (int i = 0; i < 8; i++) { m[i] = -INFINITY; p[i] = 0.f; s[i] = 0.f; }

    for (int jt = 0; jt < JTILES_PER_SPLIT; jt++) {
        const int colBase = (split * JTILES_PER_SPLIT + jt) * BN;

        __syncthreads();   // protect cmaskS readers of previous tile
        if (tid < BN) cmaskS[tid] = g_mask[colBase + tid];

        float acc[8][8];
        #pragma unroll
        for (int i = 0; i < 8; i++)
            #pragma unroll
            for (int j = 0; j < 8; j++) acc[i][j] = 0.f;

        const float* Aptr = emb + (size_t)(rowBase + lr) * DIMS + lh;
        const float* Bptr = emb + (size_t)(colBase + lr) * DIMS + lh;

        for (int k0 = 0; k0 < DIMS; k0 += BK) {
            const float4 a = *(const float4*)(Aptr + k0);
            const float4 b = *(const float4*)(Bptr + k0);
            __syncthreads();   // previous compute done before overwrite
            As[lh + 0][lr] = a.x; As[lh + 1][lr] = a.y;
            As[lh + 2][lr] = a.z; As[lh + 3][lr] = a.w;
            Bs[lh + 0][lr] = b.x; Bs[lh + 1][lr] = b.y;
            Bs[lh + 2][lr] = b.z; Bs[lh + 3][lr] = b.w;
            __syncthreads();

            #pragma unroll
            for (int kk = 0; kk < BK; kk++) {
                const float4 a0 = *(const float4*)&As[kk][ty * 8];
                const float4 a1 = *(const float4*)&As[kk][ty * 8 + 4];
                const float4 b0 = *(const float4*)&Bs[kk][tx * 8];
                const float4 b1 = *(const float4*)&Bs[kk][tx * 8 + 4];
                const float ra[8] = {a0.x, a0.y, a0.z, a0.w, a1.x, a1.y, a1.z, a1.w};
                const float rb[8] = {b0.x, b0.y, b0.z, b0.w, b1.x, b1.y, b1.z, b1.w};
                #pragma unroll
                for (int i = 0; i < 8; i++)
                    #pragma unroll
                    for (int j = 0; j < 8; j++)
                        acc[i][j] += ra[i] * rb[j];
            }
        }

        // fused epilogue: online softmax update over this 8x8 micro-tile
        #pragma unroll
        for (int i = 0; i < 8; i++) {
            const int gi = rowBase + ty * 8 + i;
            const unsigned long long mi_mask = rmaskS[ty * 8 + i];
            float mm = m[i], pp = p[i], ss = s[i];
            #pragma unroll
            for (int j = 0; j < 8; j++) {
                const int gj = colBase + tx * 8 + j;
                if (gi == gj) continue;                       // off-diagonal only
                const float v = acc[i][j] * INV_T;
                const bool pos = (mi_mask & cmaskS[tx * 8 + j]) != 0ull;
                const float nm = fmaxf(mm, v);
                const float sc = __expf(mm - nm);             // exp(-inf)=0 on first hit
                const float e  = __expf(v - nm);
                pp = pp * sc + (pos ? e : 0.f);
                ss = ss * sc + e;
                mm = nm;
            }
            m[i] = mm; p[i] = pp; s[i] = ss;
        }
    }

    // merge the 16 column-owning lanes (width-16 shfl segments)
    #pragma unroll
    for (int i = 0; i < 8; i++) {
        float mm = m[i], pp = p[i], ss = s[i];
        #pragma unroll
        for (int off = 8; off > 0; off >>= 1) {
            const float mo = __shfl_down_sync(0xffffffffu, mm, off, 16);
            const float po = __shfl_down_sync(0xffffffffu, pp, off, 16);
            const float so = __shfl_down_sync(0xffffffffu, ss, off, 16);
            const float M = fmaxf(mm, mo);
            const float f1 = __expf(mm - M);
            const float f2 = __expf(mo - M);
            pp = pp * f1 + po * f2;
            ss = ss * f1 + so * f2;
            mm = M;
        }
        if (tx == 0) {
            const int row = rowBase + ty * 8 + i;
            g_pm[split * N_ROWS + row] = mm;
            g_pp[split * N_ROWS + row] = pp;
            g_ps[split * N_ROWS + row] = ss;
        }
    }
}

// ---------------- kernel 3: merge splits, compute loss -----------------------
__global__ void final_kernel(float* __restrict__ out) {
    const int tid = threadIdx.x;          // 512 threads
    float lsum = 0.f, bsum = 0.f;
    int lcnt = 0;

    for (int row = tid; row < N_ROWS; row += 512) {
        float mm = -INFINITY, pp = 0.f, ss = 0.f;
        #pragma unroll
        for (int sp = 0; sp < SPLITS; sp++) {
            const float mo = g_pm[sp * N_ROWS + row];
            const float po = g_pp[sp * N_ROWS + row];
            const float so = g_ps[sp * N_ROWS + row];
            const float M = fmaxf(mm, mo);
            const float f1 = (mm == -INFINITY) ? 0.f : __expf(mm - M);
            const float f2 = __expf(mo - M);
            pp = pp * f1 + po * f2;
            ss = ss * f1 + so * f2;
            mm = M;
        }
        if (pp > 0.f) {                    // row has a positive pair -> valid
            lsum += -logf(pp / (ss + 1e-8f)) * g_w[row];
            lcnt++;
        }
        bsum += g_bce_part[row];
    }

    __shared__ float rs[512], rb[512];
    __shared__ int rc[512];
    rs[tid] = lsum; rb[tid] = bsum; rc[tid] = lcnt;
    __syncthreads();
    for (int off = 256; off > 0; off >>= 1) {
        if (tid < off) {
            rs[tid] += rs[tid + off];
            rb[tid] += rb[tid + off];
            rc[tid] += rc[tid + off];
        }
        __syncthreads();
    }
    if (tid == 0) {
        const float bce = rb[0] / (float)(N_ROWS * NCLS);
        const float contrastive = (rc[0] > 0) ? (rs[0] / (float)rc[0]) : 0.f;
        out[0] = bce + contrastive;       // ALPHA = 1.0
    }
}

// ---------------- launch ----------------------------------------------------
extern "C" void kernel_launch(void* const* d_in, const int* in_sizes, int n_in,
                              void* d_out, int out_size) {
    (void)in_sizes; (void)n_in; (void)out_size;
    const float* emb    = (const float*)d_in[0];
    const float* logits = (const float*)d_in[1];
    const int*   labels = (const int*)d_in[2];
    float* out = (float*)d_out;

    prep_kernel<<<N_ROWS, NCLS>>>(logits, labels);
    sim_kernel<<<dim3(N_ROWS / BM, SPLITS), 256>>>(emb);
    final_kernel<<<1, 512>>>(out);
}

// round 3
// speedup vs baseline: 3.0859x; 3.0859x over previous
#include <cuda_runtime.h>
#include <cuda_bf16.h>
#include <stdint.h>
#include <math.h>

#define N_ROWS 4096
#define DIMS   1024
#define NCLS   64
#define NT     32               // 4096/128 tiles per dim
#define INV_T  14.285714285714286f

#define NCHUNK 96               // K=3072 in BK=32 chunks
#define STAGES 4
#define STAGE_BYTES 16384       // A 8KB + B 8KB
#define SM_RMASK (STAGES * STAGE_BYTES)        // 65536
#define SM_CMASK (SM_RMASK + 1024)
#define SM_ROWP  (SM_CMASK + 1024)
#define SM_ROWS  (SM_ROWP + 512)
#define SMEM_TOTAL (SM_ROWS + 512)             // 68608 B

// ---------------- device scratch -------------------------------------------
__device__ __nv_bfloat16 g_hi[N_ROWS * DIMS];   // 8 MB
__device__ __nv_bfloat16 g_lo[N_ROWS * DIMS];   // 8 MB
__device__ unsigned long long g_mask[N_ROWS];
__device__ float g_w[N_ROWS];
__device__ float g_bce_part[N_ROWS];
__device__ float g_pp[NT * N_ROWS];
__device__ float g_ps[NT * N_ROWS];

// ---------------- PTX helpers (baseline ISA only: sm_80/75 features) --------
__device__ __forceinline__ uint32_t smem_u32(const void* p) {
    uint32_t a;
    asm("{ .reg .u64 t; cvta.to.shared.u64 t, %1; cvt.u32.u64 %0, t; }" : "=r"(a) : "l"(p));
    return a;
}
#define CP16(dst, src) \
    asm volatile("cp.async.cg.shared.global [%0], [%1], 16;" :: "r"(dst), "l"(src))
#define CP_COMMIT() asm volatile("cp.async.commit_group;")
#define CP_WAIT2()  asm volatile("cp.async.wait_group 2;")
#define LDSM4(r, a) \
    asm volatile("ldmatrix.sync.aligned.m8n8.x4.shared.b16 {%0,%1,%2,%3}, [%4];" \
        : "=r"((r)[0]), "=r"((r)[1]), "=r"((r)[2]), "=r"((r)[3]) : "r"(a))
#define MMA16816(c, a, b0, b1) \
    asm volatile("mma.sync.aligned.m16n8k16.row.col.f32.bf16.bf16.f32 " \
        "{%0,%1,%2,%3},{%4,%5,%6,%7},{%8,%9},{%0,%1,%2,%3};" \
        : "+f"((c)[0]), "+f"((c)[1]), "+f"((c)[2]), "+f"((c)[3]) \
        : "r"((a)[0]), "r"((a)[1]), "r"((a)[2]), "r"((a)[3]), "r"(b0), "r"(b1))

// ---------------- kernel A: fp32 -> (hi, lo) bf16, row-major ----------------
__global__ void convert_kernel(const float* __restrict__ emb) {
    const int idx = blockIdx.x * 256 + threadIdx.x;    // 4096*128 groups of 8
    const int r = idx >> 7;
    const int g = idx & 127;
    const float4* src = (const float4*)(emb + (size_t)r * DIMS + g * 8);
    const float4 x0 = src[0], x1 = src[1];
    const float v[8] = {x0.x, x0.y, x0.z, x0.w, x1.x, x1.y, x1.z, x1.w};
    uint32_t hw[4], lw[4];
#pragma unroll
    for (int i = 0; i < 4; i++) {
        const __nv_bfloat16 h0 = __float2bfloat16_rn(v[2*i]);
        const __nv_bfloat16 h1 = __float2bfloat16_rn(v[2*i+1]);
        const __nv_bfloat16 l0 = __float2bfloat16_rn(v[2*i]   - __bfloat162float(h0));
        const __nv_bfloat16 l1 = __float2bfloat16_rn(v[2*i+1] - __bfloat162float(h1));
        hw[i] = ((uint32_t)__bfloat16_as_ushort(h1) << 16) | __bfloat16_as_ushort(h0);
        lw[i] = ((uint32_t)__bfloat16_as_ushort(l1) << 16) | __bfloat16_as_ushort(l0);
    }
    ((uint4*)g_hi)[idx] = make_uint4(hw[0], hw[1], hw[2], hw[3]);
    ((uint4*)g_lo)[idx] = make_uint4(lw[0], lw[1], lw[2], lw[3]);
}

// ---------------- kernel B: per-row prep (BCE, weights, bitmask) ------------
__global__ void prep_kernel(const float* __restrict__ logits,
                            const int* __restrict__ labels) {
    const int row = blockIdx.x;
    const int idx = row * NCLS + threadIdx.x;
    const float x = logits[idx];
    const int lab = labels[idx];
    const float y = (float)lab;
    float bce = fmaxf(x, 0.f) - x * y + log1pf(expf(-fabsf(x)));
    const float pr = 1.f / (1.f + expf(-x));
    const float ent = -(pr * logf(pr + 1e-8f) + (1.f - pr) * logf(1.f - pr + 1e-8f));
    float wn = ent * y, wd = y;
    const unsigned bal = __ballot_sync(0xffffffffu, lab != 0);
#pragma unroll
    for (int off = 16; off > 0; off >>= 1) {
        bce += __shfl_down_sync(0xffffffffu, bce, off);
        wn  += __shfl_down_sync(0xffffffffu, wn, off);
        wd  += __shfl_down_sync(0xffffffffu, wd, off);
    }
    __shared__ float sb[2], sn[2], sd[2];
    __shared__ unsigned smk[2];
    const int w = threadIdx.x >> 5;
    if ((threadIdx.x & 31) == 0) { sb[w] = bce; sn[w] = wn; sd[w] = wd; smk[w] = bal; }
    __syncthreads();
    if (threadIdx.x == 0) {
        g_bce_part[row] = sb[0] + sb[1];
        g_w[row] = (sn[0] + sn[1]) / (sd[0] + sd[1] + 1e-8f);
        g_mask[row] = ((unsigned long long)smk[1] << 32) | (unsigned long long)smk[0];
    }
}

// ---------------- kernel C: mma.sync sim GEMM + fused softmax sums ----------
// K' = 3072:  phase 0: Ahi*Bhi   phase 1: Alo*Bhi   phase 2: Ahi*Blo
__global__ __launch_bounds__(256, 1)
void sim_kernel() {
    extern __shared__ char smem[];
    const uint32_t sbase = smem_u32(smem);
    const int tid = threadIdx.x;
    const int wid = tid >> 5, lane = tid & 31;
    const int wr = wid & 3, wc = wid >> 2;          // warp grid 4x2
    const int rowBase = blockIdx.x * 128;
    const int colBase = blockIdx.y * 128;

    unsigned long long* rmaskS = (unsigned long long*)(smem + SM_RMASK);
    unsigned long long* cmaskS = (unsigned long long*)(smem + SM_CMASK);
    float* rowP = (float*)(smem + SM_ROWP);
    float* rowS = (float*)(smem + SM_ROWS);

    if (tid < 128) {
        rmaskS[tid] = g_mask[rowBase + tid];
        cmaskS[tid] = g_mask[colBase + tid];
        rowP[tid] = 0.f;
        rowS[tid] = 0.f;
    }

    // ---- per-thread cp.async mapping: 512 16B chunks each for A and B ------
    const int lr0 = tid >> 2;                 // rows 0..63 (and +64)
    const int lg = tid & 3;                   // 16B group within 64B k-slice
    const uint32_t swzA = (lg ^ ((lr0 >> 1) & 3)) * 16;
    const uint32_t dstA0 = lr0 * 64 + swzA;          // +4096 for row+64 (same xor)
    const size_t gOffA = (size_t)(rowBase + lr0) * DIMS + lg * 8;
    const size_t gOffB = (size_t)(colBase + lr0) * DIMS + lg * 8;

    // ---- per-thread ldmatrix base addressing -------------------------------
    const int aRow = wr * 32 + (lane & 15);
    const uint32_t sA = (aRow >> 1) & 3;
    const int bRow = wc * 64 + (lane & 15);
    const uint32_t sB = (bRow >> 1) & 3;
    const uint32_t laneG = lane >> 4;

    float acc[2][8][4];
#pragma unroll
    for (int i = 0; i < 2; i++)
#pragma unroll
        for (int j = 0; j < 8; j++)
#pragma unroll
            for (int k = 0; k < 4; k++) acc[i][j][k] = 0.f;

    // ---- prologue: fill 3 stages ------------------------------------------
#pragma unroll
    for (int c = 0; c < STAGES - 1; c++) {
        const int p = c >> 5;
        const int kk = (c & 31) * 32;
        const __nv_bfloat16* As = (p == 1) ? g_lo : g_hi;
        const __nv_bfloat16* Bs = (p == 2) ? g_lo : g_hi;
        const uint32_t st = sbase + c * STAGE_BYTES;
        CP16(st + dstA0,        As + gOffA + kk);
        CP16(st + dstA0 + 4096, As + gOffA + 64 * DIMS + kk);
        CP16(st + 8192 + dstA0,        Bs + gOffB + kk);
        CP16(st + 8192 + dstA0 + 4096, Bs + gOffB + 64 * DIMS + kk);
        CP_COMMIT();
    }

    // ---- mainloop ----------------------------------------------------------
    for (int c = 0; c < NCHUNK; c++) {
        CP_WAIT2();
        __syncthreads();

        // issue loads for chunk c+3 into stage (c+3)%4  (was consumed at c-1)
        if (c + STAGES - 1 < NCHUNK) {
            const int cn = c + STAGES - 1;
            const int p = cn >> 5;
            const int kk = (cn & 31) * 32;
            const __nv_bfloat16* As = (p == 1) ? g_lo : g_hi;
            const __nv_bfloat16* Bs = (p == 2) ? g_lo : g_hi;
            const uint32_t st = sbase + (cn & 3) * STAGE_BYTES;
            CP16(st + dstA0,        As + gOffA + kk);
            CP16(st + dstA0 + 4096, As + gOffA + 64 * DIMS + kk);
            CP16(st + 8192 + dstA0,        Bs + gOffB + kk);
            CP16(st + 8192 + dstA0 + 4096, Bs + gOffB + 64 * DIMS + kk);
        }
        CP_COMMIT();

        // compute on stage c%4
        const uint32_t st = sbase + (c & 3) * STAGE_BYTES;
#pragma unroll
        for (int ks = 0; ks < 2; ks++) {
            uint32_t a0[4], a1[4], b[4][4];
            const uint32_t gk = (uint32_t)(ks * 2) + laneG;
            LDSM4(a0, st + aRow * 64        + ((gk ^ sA) * 16));
            LDSM4(a1, st + (aRow + 16) * 64 + ((gk ^ sA) * 16));
#pragma unroll
            for (int n16 = 0; n16 < 4; n16++)
                LDSM4(b[n16], st + 8192 + (bRow + n16 * 16) * 64 + ((gk ^ sB) * 16));
#pragma unroll
            for (int nt = 0; nt < 8; nt++) {
                const int n16 = nt >> 1, h = nt & 1;
                MMA16816(acc[0][nt], a0, b[n16][h], b[n16][h + 2]);
                MMA16816(acc[1][nt], a1, b[n16][h], b[n16][h + 2]);
            }
        }
    }

    // ---- fused epilogue: exp + masks + per-row pos/neg sums ----------------
    const int g8 = lane >> 2;        // quad row
    const int cq = (lane & 3) * 2;   // quad col pair
#pragma unroll
    for (int mt = 0; mt < 2; mt++) {
#pragma unroll
        for (int h = 0; h < 2; h++) {
            const int rl = wr * 32 + mt * 16 + h * 8 + g8;
            const int gi = rowBase + rl;
            const unsigned long long rm = rmaskS[rl];
            float pa = 0.f, sa = 0.f;
#pragma unroll
            for (int nt = 0; nt < 8; nt++) {
#pragma unroll
                for (int j = 0; j < 2; j++) {
                    const int cl = wc * 64 + nt * 8 + cq + j;
                    if (colBase + cl != gi) {
                        const float e = __expf(acc[mt][nt][h * 2 + j] * INV_T);
                        sa += e;
                        if (rm & cmaskS[cl]) pa += e;
                    }
                }
            }
            // reduce across the 4 lanes of the quad (same row)
            pa += __shfl_xor_sync(0xffffffffu, pa, 1);
            pa += __shfl_xor_sync(0xffffffffu, pa, 2);
            sa += __shfl_xor_sync(0xffffffffu, sa, 1);
            sa += __shfl_xor_sync(0xffffffffu, sa, 2);
            if ((lane & 3) == 0) {
                atomicAdd(&rowP[rl], pa);
                atomicAdd(&rowS[rl], sa);
            }
        }
    }
    __syncthreads();
    if (tid < 128) {
        g_pp[blockIdx.y * N_ROWS + rowBase + tid] = rowP[tid];
        g_ps[blockIdx.y * N_ROWS + rowBase + tid] = rowS[tid];
    }
}

// ---------------- kernel D: merge col-tile partials, compute loss -----------
__global__ void final_kernel(float* __restrict__ out) {
    const int tid = threadIdx.x;          // 512 threads
    float lsum = 0.f, bsum = 0.f;
    int lcnt = 0;
    for (int row = tid; row < N_ROWS; row += 512) {
        float pp = 0.f, ss = 0.f;
#pragma unroll
        for (int sp = 0; sp < NT; sp++) {
            pp += g_pp[sp * N_ROWS + row];
            ss += g_ps[sp * N_ROWS + row];
        }
        if (pp > 0.f) {
            lsum += -logf(pp / (ss + 1e-8f)) * g_w[row];
            lcnt++;
        }
        bsum += g_bce_part[row];
    }
    __shared__ float rs[512], rb[512];
    __shared__ int rc[512];
    rs[tid] = lsum; rb[tid] = bsum; rc[tid] = lcnt;
    __syncthreads();
    for (int off = 256; off > 0; off >>= 1) {
        if (tid < off) { rs[tid] += rs[tid+off]; rb[tid] += rb[tid+off]; rc[tid] += rc[tid+off]; }
        __syncthreads();
    }
    if (tid == 0) {
        const float bce = rb[0] / (float)(N_ROWS * NCLS);
        out[0] = bce + ((rc[0] > 0) ? (rs[0] / (float)rc[0]) : 0.f);
    }
}

// ---------------- launch ----------------------------------------------------
extern "C" void kernel_launch(void* const* d_in, const int* in_sizes, int n_in,
                              void* d_out, int out_size) {
    (void)in_sizes; (void)n_in; (void)out_size;
    const float* emb    = (const float*)d_in[0];
    const float* logits = (const float*)d_in[1];
    const int*   labels = (const int*)d_in[2];
    float* out = (float*)d_out;

    cudaFuncSetAttribute(sim_kernel, cudaFuncAttributeMaxDynamicSharedMemorySize, SMEM_TOTAL);

    convert_kernel<<<2048, 256>>>(emb);
    prep_kernel<<<N_ROWS, NCLS>>>(logits, labels);
    sim_kernel<<<dim3(NT, NT), 256, SMEM_TOTAL>>>();
    final_kernel<<<1, 512>>>(out);
}

// round 4
// speedup vs baseline: 3.3797x; 1.0952x over previous
#include <cuda_runtime.h>
#include <cuda_bf16.h>
#include <stdint.h>
#include <math.h>

#define N_ROWS 4096
#define DIMS   1024
#define NCLS   64
#define NT     32               // 4096/128 tiles per dim
#define NTRI   (NT * (NT + 1) / 2)   // 528 lower-triangular tiles
#define INV_T  14.285714285714286f

#define NCHUNK 96               // K=3072 in BK=32 chunks
#define STAGES 4
#define STAGE_BYTES 16384       // A 8KB + B 8KB
#define SM_RMASK (STAGES * STAGE_BYTES)        // 65536
#define SM_CMASK (SM_RMASK + 1024)
#define SM_ROWP  (SM_CMASK + 1024)
#define SM_ROWS  (SM_ROWP + 512)
#define SM_COLP  (SM_ROWS + 512)
#define SM_COLS  (SM_COLP + 512)
#define SMEM_TOTAL (SM_COLS + 512)             // 69632 B

// ---------------- device scratch -------------------------------------------
__device__ __nv_bfloat16 g_hi[N_ROWS * DIMS];   // 8 MB
__device__ __nv_bfloat16 g_lo[N_ROWS * DIMS];   // 8 MB
__device__ unsigned long long g_mask[N_ROWS];
__device__ float g_w[N_ROWS];
__device__ float g_bce_part[N_ROWS];
__device__ float g_pp[NT * N_ROWS];
__device__ float g_ps[NT * N_ROWS];
__device__ float g_fl[NT], g_fb[NT];
__device__ int   g_fc[NT];

// ---------------- PTX helpers (baseline ISA only) ----------------------------
__device__ __forceinline__ uint32_t smem_u32(const void* p) {
    uint32_t a;
    asm("{ .reg .u64 t; cvta.to.shared.u64 t, %1; cvt.u32.u64 %0, t; }" : "=r"(a) : "l"(p));
    return a;
}
#define CP16(dst, src) \
    asm volatile("cp.async.cg.shared.global [%0], [%1], 16;" :: "r"(dst), "l"(src))
#define CP_COMMIT() asm volatile("cp.async.commit_group;")
#define CP_WAIT2()  asm volatile("cp.async.wait_group 2;")
#define LDSM4(r, a) \
    asm volatile("ldmatrix.sync.aligned.m8n8.x4.shared.b16 {%0,%1,%2,%3}, [%4];" \
        : "=r"((r)[0]), "=r"((r)[1]), "=r"((r)[2]), "=r"((r)[3]) : "r"(a))
#define MMA16816(c, a, b0, b1) \
    asm volatile("mma.sync.aligned.m16n8k16.row.col.f32.bf16.bf16.f32 " \
        "{%0,%1,%2,%3},{%4,%5,%6,%7},{%8,%9},{%0,%1,%2,%3};" \
        : "+f"((c)[0]), "+f"((c)[1]), "+f"((c)[2]), "+f"((c)[3]) \
        : "r"((a)[0]), "r"((a)[1]), "r"((a)[2]), "r"((a)[3]), "r"(b0), "r"(b1))

// ---------------- kernel A: fp32 -> (hi, lo) bf16, row-major ----------------
__global__ void convert_kernel(const float* __restrict__ emb) {
    const int idx = blockIdx.x * 256 + threadIdx.x;
    const int r = idx >> 7;
    const int g = idx & 127;
    const float4* src = (const float4*)(emb + (size_t)r * DIMS + g * 8);
    const float4 x0 = src[0], x1 = src[1];
    const float v[8] = {x0.x, x0.y, x0.z, x0.w, x1.x, x1.y, x1.z, x1.w};
    uint32_t hw[4], lw[4];
#pragma unroll
    for (int i = 0; i < 4; i++) {
        const __nv_bfloat16 h0 = __float2bfloat16_rn(v[2*i]);
        const __nv_bfloat16 h1 = __float2bfloat16_rn(v[2*i+1]);
        const __nv_bfloat16 l0 = __float2bfloat16_rn(v[2*i]   - __bfloat162float(h0));
        const __nv_bfloat16 l1 = __float2bfloat16_rn(v[2*i+1] - __bfloat162float(h1));
        hw[i] = ((uint32_t)__bfloat16_as_ushort(h1) << 16) | __bfloat16_as_ushort(h0);
        lw[i] = ((uint32_t)__bfloat16_as_ushort(l1) << 16) | __bfloat16_as_ushort(l0);
    }
    ((uint4*)g_hi)[idx] = make_uint4(hw[0], hw[1], hw[2], hw[3]);
    ((uint4*)g_lo)[idx] = make_uint4(lw[0], lw[1], lw[2], lw[3]);
}

// ---------------- kernel B: per-row prep (BCE, weights, bitmask) ------------
__global__ void prep_kernel(const float* __restrict__ logits,
                            const int* __restrict__ labels) {
    const int row = blockIdx.x;
    const int idx = row * NCLS + threadIdx.x;
    const float x = logits[idx];
    const int lab = labels[idx];
    const float y = (float)lab;
    float bce = fmaxf(x, 0.f) - x * y + log1pf(expf(-fabsf(x)));
    const float pr = 1.f / (1.f + expf(-x));
    const float ent = -(pr * logf(pr + 1e-8f) + (1.f - pr) * logf(1.f - pr + 1e-8f));
    float wn = ent * y, wd = y;
    const unsigned bal = __ballot_sync(0xffffffffu, lab != 0);
#pragma unroll
    for (int off = 16; off > 0; off >>= 1) {
        bce += __shfl_down_sync(0xffffffffu, bce, off);
        wn  += __shfl_down_sync(0xffffffffu, wn, off);
        wd  += __shfl_down_sync(0xffffffffu, wd, off);
    }
    __shared__ float sb[2], sn[2], sd[2];
    __shared__ unsigned smk[2];
    const int w = threadIdx.x >> 5;
    if ((threadIdx.x & 31) == 0) { sb[w] = bce; sn[w] = wn; sd[w] = wd; smk[w] = bal; }
    __syncthreads();
    if (threadIdx.x == 0) {
        g_bce_part[row] = sb[0] + sb[1];
        g_w[row] = (sn[0] + sn[1]) / (sd[0] + sd[1] + 1e-8f);
        g_mask[row] = ((unsigned long long)smk[1] << 32) | (unsigned long long)smk[0];
    }
}

// ---------------- kernel C: symmetric mma.sync GEMM + fused softmax sums ----
// 528 lower-triangular tiles; off-diagonal tiles emit both row sums (block I
// into slot J) and, via symmetry, col sums (block J into slot I).
__global__ __launch_bounds__(256, 1)
void sim_kernel() {
    extern __shared__ char smem[];
    const uint32_t sbase = smem_u32(smem);
    const int tid = threadIdx.x;
    const int wid = tid >> 5, lane = tid & 31;
    const int wr = wid & 3, wc = wid >> 2;          // warp grid 4x2

    // map linear bid -> (I, J), J <= I
    const int bid = blockIdx.x;
    int I = (int)((sqrtf(8.f * (float)bid + 1.f) - 1.f) * 0.5f);
    while ((I + 1) * (I + 2) / 2 <= bid) I++;
    while (I * (I + 1) / 2 > bid) I--;
    const int J = bid - I * (I + 1) / 2;
    const bool isDiag = (I == J);
    const int rowBase = I * 128;
    const int colBase = J * 128;

    unsigned long long* rmaskS = (unsigned long long*)(smem + SM_RMASK);
    unsigned long long* cmaskS = (unsigned long long*)(smem + SM_CMASK);
    float* rowP = (float*)(smem + SM_ROWP);
    float* rowS = (float*)(smem + SM_ROWS);
    float* colP = (float*)(smem + SM_COLP);
    float* colS = (float*)(smem + SM_COLS);

    if (tid < 128) {
        rmaskS[tid] = g_mask[rowBase + tid];
        cmaskS[tid] = g_mask[colBase + tid];
        rowP[tid] = 0.f; rowS[tid] = 0.f;
        colP[tid] = 0.f; colS[tid] = 0.f;
    }

    // ---- cp.async mapping ---------------------------------------------------
    const int lr0 = tid >> 2;
    const int lg = tid & 3;
    const uint32_t swzA = (lg ^ ((lr0 >> 1) & 3)) * 16;
    const uint32_t dstA0 = lr0 * 64 + swzA;
    const size_t gOffA = (size_t)(rowBase + lr0) * DIMS + lg * 8;
    const size_t gOffB = (size_t)(colBase + lr0) * DIMS + lg * 8;

    // ---- ldmatrix addressing -------------------------------------------------
    const int aRow = wr * 32 + (lane & 15);
    const uint32_t sA = (aRow >> 1) & 3;
    const int bRow = wc * 64 + (lane & 15);
    const uint32_t sB = (bRow >> 1) & 3;
    const uint32_t laneG = lane >> 4;

    float acc[2][8][4];
#pragma unroll
    for (int i = 0; i < 2; i++)
#pragma unroll
        for (int j = 0; j < 8; j++)
#pragma unroll
            for (int k = 0; k < 4; k++) acc[i][j][k] = 0.f;

#pragma unroll
    for (int c = 0; c < STAGES - 1; c++) {
        const int p = c >> 5;
        const int kk = (c & 31) * 32;
        const __nv_bfloat16* As = (p == 1) ? g_lo : g_hi;
        const __nv_bfloat16* Bs = (p == 2) ? g_lo : g_hi;
        const uint32_t st = sbase + c * STAGE_BYTES;
        CP16(st + dstA0,        As + gOffA + kk);
        CP16(st + dstA0 + 4096, As + gOffA + 64 * DIMS + kk);
        CP16(st + 8192 + dstA0,        Bs + gOffB + kk);
        CP16(st + 8192 + dstA0 + 4096, Bs + gOffB + 64 * DIMS + kk);
        CP_COMMIT();
    }

    for (int c = 0; c < NCHUNK; c++) {
        CP_WAIT2();
        __syncthreads();
        if (c + STAGES - 1 < NCHUNK) {
            const int cn = c + STAGES - 1;
            const int p = cn >> 5;
            const int kk = (cn & 31) * 32;
            const __nv_bfloat16* As = (p == 1) ? g_lo : g_hi;
            const __nv_bfloat16* Bs = (p == 2) ? g_lo : g_hi;
            const uint32_t st = sbase + (cn & 3) * STAGE_BYTES;
            CP16(st + dstA0,        As + gOffA + kk);
            CP16(st + dstA0 + 4096, As + gOffA + 64 * DIMS + kk);
            CP16(st + 8192 + dstA0,        Bs + gOffB + kk);
            CP16(st + 8192 + dstA0 + 4096, Bs + gOffB + 64 * DIMS + kk);
        }
        CP_COMMIT();

        const uint32_t st = sbase + (c & 3) * STAGE_BYTES;
#pragma unroll
        for (int ks = 0; ks < 2; ks++) {
            uint32_t a0[4], a1[4], b[4][4];
            const uint32_t gk = (uint32_t)(ks * 2) + laneG;
            LDSM4(a0, st + aRow * 64        + ((gk ^ sA) * 16));
            LDSM4(a1, st + (aRow + 16) * 64 + ((gk ^ sA) * 16));
#pragma unroll
            for (int n16 = 0; n16 < 4; n16++)
                LDSM4(b[n16], st + 8192 + (bRow + n16 * 16) * 64 + ((gk ^ sB) * 16));
#pragma unroll
            for (int nt = 0; nt < 8; nt++) {
                const int n16 = nt >> 1, h = nt & 1;
                MMA16816(acc[0][nt], a0, b[n16][h], b[n16][h + 2]);
                MMA16816(acc[1][nt], a1, b[n16][h], b[n16][h + 2]);
            }
        }
    }

    // ---- fused epilogue ------------------------------------------------------
    const int g8 = lane >> 2;        // quad row 0..7
    const int cq = (lane & 3) * 2;   // quad col pair
    float cp[8][2], cs[8][2];
#pragma unroll
    for (int nt = 0; nt < 8; nt++) { cp[nt][0]=cp[nt][1]=cs[nt][0]=cs[nt][1]=0.f; }

#pragma unroll
    for (int mt = 0; mt < 2; mt++) {
#pragma unroll
        for (int h = 0; h < 2; h++) {
            const int rl = wr * 32 + mt * 16 + h * 8 + g8;
            const int gi = rowBase + rl;
            const unsigned long long rm = rmaskS[rl];
            float pa = 0.f, sa = 0.f;
#pragma unroll
            for (int nt = 0; nt < 8; nt++) {
#pragma unroll
                for (int j = 0; j < 2; j++) {
                    const int cl = wc * 64 + nt * 8 + cq + j;
                    if (!isDiag || colBase + cl != gi) {
                        const float e = __expf(acc[mt][nt][h * 2 + j] * INV_T);
                        const bool pos = (rm & cmaskS[cl]) != 0ull;
                        sa += e;
                        if (pos) pa += e;
                        cs[nt][j] += e;
                        if (pos) cp[nt][j] += e;
                    }
                }
            }
            pa += __shfl_xor_sync(0xffffffffu, pa, 1);
            pa += __shfl_xor_sync(0xffffffffu, pa, 2);
            sa += __shfl_xor_sync(0xffffffffu, sa, 1);
            sa += __shfl_xor_sync(0xffffffffu, sa, 2);
            if ((lane & 3) == 0) {
                atomicAdd(&rowP[rl], pa);
                atomicAdd(&rowS[rl], sa);
            }
        }
    }

    // col reductions (only needed off-diagonal): reduce over quad-row axis
    if (!isDiag) {
#pragma unroll
        for (int nt = 0; nt < 8; nt++) {
#pragma unroll
            for (int j = 0; j < 2; j++) {
                float p = cp[nt][j], s = cs[nt][j];
#pragma unroll
                for (int off = 4; off < 32; off <<= 1) {
                    p += __shfl_xor_sync(0xffffffffu, p, off);
                    s += __shfl_xor_sync(0xffffffffu, s, off);
                }
                if (g8 == 0) {
                    const int cl = wc * 64 + nt * 8 + cq + j;
                    atomicAdd(&colP[cl], p);
                    atomicAdd(&colS[cl], s);
                }
            }
        }
    }

    __syncthreads();
    if (tid < 128) {
        g_pp[J * N_ROWS + rowBase + tid] = rowP[tid];
        g_ps[J * N_ROWS + rowBase + tid] = rowS[tid];
        if (!isDiag) {
            g_pp[I * N_ROWS + colBase + tid] = colP[tid];
            g_ps[I * N_ROWS + colBase + tid] = colS[tid];
        }
    }
}

// ---------------- kernel D1: per-row loss, block partials --------------------
__global__ void final1_kernel() {
    const int row = blockIdx.x * 128 + threadIdx.x;
    float pp = 0.f, ss = 0.f;
#pragma unroll
    for (int sp = 0; sp < NT; sp++) {
        pp += g_pp[sp * N_ROWS + row];
        ss += g_ps[sp * N_ROWS + row];
    }
    float ls = 0.f;
    int c = 0;
    if (pp > 0.f) { ls = -logf(pp / (ss + 1e-8f)) * g_w[row]; c = 1; }
    float bs = g_bce_part[row];

    const int lane = threadIdx.x & 31;
#pragma unroll
    for (int off = 16; off > 0; off >>= 1) {
        ls += __shfl_down_sync(0xffffffffu, ls, off);
        bs += __shfl_down_sync(0xffffffffu, bs, off);
        c  += __shfl_down_sync(0xffffffffu, c, off);
    }
    __shared__ float wl[4], wb[4];
    __shared__ int wc_[4];
    const int w = threadIdx.x >> 5;
    if (lane == 0) { wl[w] = ls; wb[w] = bs; wc_[w] = c; }
    __syncthreads();
    if (threadIdx.x == 0) {
        g_fl[blockIdx.x] = wl[0] + wl[1] + wl[2] + wl[3];
        g_fb[blockIdx.x] = wb[0] + wb[1] + wb[2] + wb[3];
        g_fc[blockIdx.x] = wc_[0] + wc_[1] + wc_[2] + wc_[3];
    }
}

// ---------------- kernel D2: combine 32 partials -----------------------------
__global__ void final2_kernel(float* __restrict__ out) {
    const int lane = threadIdx.x;      // 32 threads
    float ls = g_fl[lane], bs = g_fb[lane];
    int c = g_fc[lane];
#pragma unroll
    for (int off = 16; off > 0; off >>= 1) {
        ls += __shfl_down_sync(0xffffffffu, ls, off);
        bs += __shfl_down_sync(0xffffffffu, bs, off);
        c  += __shfl_down_sync(0xffffffffu, c, off);
    }
    if (lane == 0) {
        const float bce = bs / (float)(N_ROWS * NCLS);
        out[0] = bce + ((c > 0) ? (ls / (float)c) : 0.f);
    }
}

// ---------------- launch ------------------------------------------------------
extern "C" void kernel_launch(void* const* d_in, const int* in_sizes, int n_in,
                              void* d_out, int out_size) {
    (void)in_sizes; (void)n_in; (void)out_size;
    const float* emb    = (const float*)d_in[0];
    const float* logits = (const float*)d_in[1];
    const int*   labels = (const int*)d_in[2];
    float* out = (float*)d_out;

    cudaFuncSetAttribute(sim_kernel, cudaFuncAttributeMaxDynamicSharedMemorySize, SMEM_TOTAL);

    convert_kernel<<<2048, 256>>>(emb);
    prep_kernel<<<N_ROWS, NCLS>>>(logits, labels);
    sim_kernel<<<NTRI, 256, SMEM_TOTAL>>>();
    final1_kernel<<<NT, 128>>>();
    final2_kernel<<<1, 32>>>(out);
}

// round 5
// speedup vs baseline: 5.0382x; 1.4907x over previous
#include <cuda_runtime.h>
#include <cuda_bf16.h>
#include <stdint.h>
#include <math.h>

#define N_ROWS 4096
#define DIMS   1024
#define NCLS   64
#define NT     32               // 4096/128 tiles per dim
#define NTRI   (NT * (NT + 1) / 2)   // 528 lower-triangular tiles
#define INV_T  14.285714285714286f

#define NCHUNK 96               // K=3072 in BK=32 chunks
#define STAGES 3
#define STAGE_BYTES 16384       // A 8KB + B 8KB
#define SM_RMASK (STAGES * STAGE_BYTES)        // 49152
#define SM_CMASK (SM_RMASK + 1024)
#define SM_ROWP  (SM_CMASK + 1024)
#define SM_ROWS  (SM_ROWP + 512)
#define SM_COLP  (SM_ROWS + 512)
#define SM_COLS  (SM_COLP + 512)
#define SMEM_TOTAL (SM_COLS + 512)             // 53248 B -> 2 CTAs/SM

// ---------------- device scratch -------------------------------------------
__device__ __nv_bfloat16 g_hi[N_ROWS * DIMS];   // 8 MB
__device__ __nv_bfloat16 g_lo[N_ROWS * DIMS];   // 8 MB
__device__ unsigned long long g_mask[N_ROWS];
__device__ float g_w[N_ROWS];
__device__ float g_bce_part[N_ROWS];
__device__ float g_pp[NT * N_ROWS];
__device__ float g_ps[NT * N_ROWS];
__device__ float g_fl[NT], g_fb[NT];
__device__ int   g_fc[NT];

// ---------------- PTX helpers (baseline ISA only) ----------------------------
__device__ __forceinline__ uint32_t smem_u32(const void* p) {
    uint32_t a;
    asm("{ .reg .u64 t; cvta.to.shared.u64 t, %1; cvt.u32.u64 %0, t; }" : "=r"(a) : "l"(p));
    return a;
}
#define CP16(dst, src) \
    asm volatile("cp.async.cg.shared.global [%0], [%1], 16;" :: "r"(dst), "l"(src))
#define CP_COMMIT() asm volatile("cp.async.commit_group;")
#define CP_WAIT1()  asm volatile("cp.async.wait_group 1;")
#define LDSM4(r, a) \
    asm volatile("ldmatrix.sync.aligned.m8n8.x4.shared.b16 {%0,%1,%2,%3}, [%4];" \
        : "=r"((r)[0]), "=r"((r)[1]), "=r"((r)[2]), "=r"((r)[3]) : "r"(a))
#define MMA16816(c, a, b0, b1) \
    asm volatile("mma.sync.aligned.m16n8k16.row.col.f32.bf16.bf16.f32 " \
        "{%0,%1,%2,%3},{%4,%5,%6,%7},{%8,%9},{%0,%1,%2,%3};" \
        : "+f"((c)[0]), "+f"((c)[1]), "+f"((c)[2]), "+f"((c)[3]) \
        : "r"((a)[0]), "r"((a)[1]), "r"((a)[2]), "r"((a)[3]), "r"(b0), "r"(b1))

// ---------------- kernel A: fp32 -> (hi, lo) bf16, row-major ----------------
__global__ void convert_kernel(const float* __restrict__ emb) {
    const int idx = blockIdx.x * 256 + threadIdx.x;
    const float4* src = (const float4*)(emb + (size_t)idx * 8);
    const float4 x0 = src[0], x1 = src[1];
    const float v[8] = {x0.x, x0.y, x0.z, x0.w, x1.x, x1.y, x1.z, x1.w};
    uint32_t hw[4], lw[4];
#pragma unroll
    for (int i = 0; i < 4; i++) {
        const __nv_bfloat16 h0 = __float2bfloat16_rn(v[2*i]);
        const __nv_bfloat16 h1 = __float2bfloat16_rn(v[2*i+1]);
        const __nv_bfloat16 l0 = __float2bfloat16_rn(v[2*i]   - __bfloat162float(h0));
        const __nv_bfloat16 l1 = __float2bfloat16_rn(v[2*i+1] - __bfloat162float(h1));
        hw[i] = ((uint32_t)__bfloat16_as_ushort(h1) << 16) | __bfloat16_as_ushort(h0);
        lw[i] = ((uint32_t)__bfloat16_as_ushort(l1) << 16) | __bfloat16_as_ushort(l0);
    }
    ((uint4*)g_hi)[idx] = make_uint4(hw[0], hw[1], hw[2], hw[3]);
    ((uint4*)g_lo)[idx] = make_uint4(lw[0], lw[1], lw[2], lw[3]);
}

// ---------------- kernel B: per-row prep (BCE, weights, bitmask) ------------
__global__ void prep_kernel(const float* __restrict__ logits,
                            const int* __restrict__ labels) {
    const int row = blockIdx.x;
    const int idx = row * NCLS + threadIdx.x;
    const float x = logits[idx];
    const int lab = labels[idx];
    const float y = (float)lab;
    float bce = fmaxf(x, 0.f) - x * y + log1pf(expf(-fabsf(x)));
    const float pr = 1.f / (1.f + expf(-x));
    const float ent = -(pr * logf(pr + 1e-8f) + (1.f - pr) * logf(1.f - pr + 1e-8f));
    float wn = ent * y, wd = y;
    const unsigned bal = __ballot_sync(0xffffffffu, lab != 0);
#pragma unroll
    for (int off = 16; off > 0; off >>= 1) {
        bce += __shfl_down_sync(0xffffffffu, bce, off);
        wn  += __shfl_down_sync(0xffffffffu, wn, off);
        wd  += __shfl_down_sync(0xffffffffu, wd, off);
    }
    __shared__ float sb[2], sn[2], sd[2];
    __shared__ unsigned smk[2];
    const int w = threadIdx.x >> 5;
    if ((threadIdx.x & 31) == 0) { sb[w] = bce; sn[w] = wn; sd[w] = wd; smk[w] = bal; }
    __syncthreads();
    if (threadIdx.x == 0) {
        g_bce_part[row] = sb[0] + sb[1];
        g_w[row] = (sn[0] + sn[1]) / (sd[0] + sd[1] + 1e-8f);
        g_mask[row] = ((unsigned long long)smk[1] << 32) | (unsigned long long)smk[0];
    }
}

// ---------------- kernel C: symmetric mma.sync GEMM + fused softmax sums ----
__global__ __launch_bounds__(256, 2)
void sim_kernel() {
    extern __shared__ char smem[];
    const uint32_t sbase = smem_u32(smem);
    const int tid = threadIdx.x;
    const int wid = tid >> 5, lane = tid & 31;
    const int wr = wid & 3, wc = wid >> 2;          // warp grid 4x2

    // map linear bid -> (I, J), J <= I
    const int bid = blockIdx.x;
    int I = (int)((sqrtf(8.f * (float)bid + 1.f) - 1.f) * 0.5f);
    while ((I + 1) * (I + 2) / 2 <= bid) I++;
    while (I * (I + 1) / 2 > bid) I--;
    const int J = bid - I * (I + 1) / 2;
    const bool isDiag = (I == J);
    const int rowBase = I * 128;
    const int colBase = J * 128;

    unsigned long long* rmaskS = (unsigned long long*)(smem + SM_RMASK);
    unsigned long long* cmaskS = (unsigned long long*)(smem + SM_CMASK);
    float* rowP = (float*)(smem + SM_ROWP);
    float* rowS = (float*)(smem + SM_ROWS);
    float* colP = (float*)(smem + SM_COLP);
    float* colS = (float*)(smem + SM_COLS);

    if (tid < 128) {
        rmaskS[tid] = g_mask[rowBase + tid];
        cmaskS[tid] = g_mask[colBase + tid];
        rowP[tid] = 0.f; rowS[tid] = 0.f;
        colP[tid] = 0.f; colS[tid] = 0.f;
    }

    // ---- cp.async mapping ---------------------------------------------------
    const int lr0 = tid >> 2;
    const int lg = tid & 3;
    const uint32_t swzA = (lg ^ ((lr0 >> 1) & 3)) * 16;
    const uint32_t dstA0 = lr0 * 64 + swzA;
    const size_t gOffA = (size_t)(rowBase + lr0) * DIMS + lg * 8;
    const size_t gOffB = (size_t)(colBase + lr0) * DIMS + lg * 8;

    // ---- ldmatrix addressing -------------------------------------------------
    const int aRow = wr * 32 + (lane & 15);
    const uint32_t sA = (aRow >> 1) & 3;
    const int bRow = wc * 64 + (lane & 15);
    const uint32_t sB = (bRow >> 1) & 3;
    const uint32_t laneG = lane >> 4;

    float acc[2][8][4];
#pragma unroll
    for (int i = 0; i < 2; i++)
#pragma unroll
        for (int j = 0; j < 8; j++)
#pragma unroll
            for (int k = 0; k < 4; k++) acc[i][j][k] = 0.f;

    // prologue: fill stages 0..STAGES-2
#pragma unroll
    for (int c = 0; c < STAGES - 1; c++) {
        const int p = c >> 5;
        const int kk = (c & 31) * 32;
        const __nv_bfloat16* As = (p == 1) ? g_lo : g_hi;
        const __nv_bfloat16* Bs = (p == 2) ? g_lo : g_hi;
        const uint32_t st = sbase + c * STAGE_BYTES;
        CP16(st + dstA0,        As + gOffA + kk);
        CP16(st + dstA0 + 4096, As + gOffA + 64 * DIMS + kk);
        CP16(st + 8192 + dstA0,        Bs + gOffB + kk);
        CP16(st + 8192 + dstA0 + 4096, Bs + gOffB + 64 * DIMS + kk);
        CP_COMMIT();
    }

    for (int c = 0; c < NCHUNK; c++) {
        CP_WAIT1();
        __syncthreads();
        // issue chunk c+2 into stage (c+2)%3 (consumed at iter c-1; sync above)
        if (c + STAGES - 1 < NCHUNK) {
            const int cn = c + STAGES - 1;
            const int p = cn >> 5;
            const int kk = (cn & 31) * 32;
            const __nv_bfloat16* As = (p == 1) ? g_lo : g_hi;
            const __nv_bfloat16* Bs = (p == 2) ? g_lo : g_hi;
            const uint32_t st = sbase + (cn % STAGES) * STAGE_BYTES;
            CP16(st + dstA0,        As + gOffA + kk);
            CP16(st + dstA0 + 4096, As + gOffA + 64 * DIMS + kk);
            CP16(st + 8192 + dstA0,        Bs + gOffB + kk);
            CP16(st + 8192 + dstA0 + 4096, Bs + gOffB + 64 * DIMS + kk);
        }
        CP_COMMIT();

        const uint32_t st = sbase + (c % STAGES) * STAGE_BYTES;
#pragma unroll
        for (int ks = 0; ks < 2; ks++) {
            uint32_t a0[4], a1[4], b[4][4];
            const uint32_t gk = (uint32_t)(ks * 2) + laneG;
            LDSM4(a0, st + aRow * 64        + ((gk ^ sA) * 16));
            LDSM4(a1, st + (aRow + 16) * 64 + ((gk ^ sA) * 16));
#pragma unroll
            for (int n16 = 0; n16 < 4; n16++)
                LDSM4(b[n16], st + 8192 + (bRow + n16 * 16) * 64 + ((gk ^ sB) * 16));
#pragma unroll
            for (int nt = 0; nt < 8; nt++) {
                const int n16 = nt >> 1, h = nt & 1;
                MMA16816(acc[0][nt], a0, b[n16][h], b[n16][h + 2]);
                MMA16816(acc[1][nt], a1, b[n16][h], b[n16][h + 2]);
            }
        }
    }

    // ---- fused epilogue ------------------------------------------------------
    const int g8 = lane >> 2;        // quad row 0..7
    const int cq = (lane & 3) * 2;   // quad col pair
    float cp[8][2], cs[8][2];
#pragma unroll
    for (int nt = 0; nt < 8; nt++) { cp[nt][0]=cp[nt][1]=cs[nt][0]=cs[nt][1]=0.f; }

#pragma unroll
    for (int mt = 0; mt < 2; mt++) {
#pragma unroll
        for (int h = 0; h < 2; h++) {
            const int rl = wr * 32 + mt * 16 + h * 8 + g8;
            const int gi = rowBase + rl;
            const unsigned long long rm = rmaskS[rl];
            float pa = 0.f, sa = 0.f;
#pragma unroll
            for (int nt = 0; nt < 8; nt++) {
#pragma unroll
                for (int j = 0; j < 2; j++) {
                    const int cl = wc * 64 + nt * 8 + cq + j;
                    if (!isDiag || colBase + cl != gi) {
                        const float e = __expf(acc[mt][nt][h * 2 + j] * INV_T);
                        const bool pos = (rm & cmaskS[cl]) != 0ull;
                        sa += e;
                        if (pos) pa += e;
                        cs[nt][j] += e;
                        if (pos) cp[nt][j] += e;
                    }
                }
            }
            pa += __shfl_xor_sync(0xffffffffu, pa, 1);
            pa += __shfl_xor_sync(0xffffffffu, pa, 2);
            sa += __shfl_xor_sync(0xffffffffu, sa, 1);
            sa += __shfl_xor_sync(0xffffffffu, sa, 2);
            if ((lane & 3) == 0) {
                atomicAdd(&rowP[rl], pa);
                atomicAdd(&rowS[rl], sa);
            }
        }
    }

    if (!isDiag) {
#pragma unroll
        for (int nt = 0; nt < 8; nt++) {
#pragma unroll
            for (int j = 0; j < 2; j++) {
                float p = cp[nt][j], s = cs[nt][j];
#pragma unroll
                for (int off = 4; off < 32; off <<= 1) {
                    p += __shfl_xor_sync(0xffffffffu, p, off);
                    s += __shfl_xor_sync(0xffffffffu, s, off);
                }
                if (g8 == 0) {
                    const int cl = wc * 64 + nt * 8 + cq + j;
                    atomicAdd(&colP[cl], p);
                    atomicAdd(&colS[cl], s);
                }
            }
        }
    }

    __syncthreads();
    if (tid < 128) {
        g_pp[J * N_ROWS + rowBase + tid] = rowP[tid];
        g_ps[J * N_ROWS + rowBase + tid] = rowS[tid];
        if (!isDiag) {
            g_pp[I * N_ROWS + colBase + tid] = colP[tid];
            g_ps[I * N_ROWS + colBase + tid] = colS[tid];
        }
    }
}

// ---------------- kernel D1: per-row loss, block partials --------------------
__global__ void final1_kernel() {
    const int row = blockIdx.x * 128 + threadIdx.x;
    float pp = 0.f, ss = 0.f;
#pragma unroll
    for (int sp = 0; sp < NT; sp++) {
        pp += g_pp[sp * N_ROWS + row];
        ss += g_ps[sp * N_ROWS + row];
    }
    float ls = 0.f;
    int c = 0;
    if (pp > 0.f) { ls = -logf(pp / (ss + 1e-8f)) * g_w[row]; c = 1; }
    float bs = g_bce_part[row];

    const int lane = threadIdx.x & 31;
#pragma unroll
    for (int off = 16; off > 0; off >>= 1) {
        ls += __shfl_down_sync(0xffffffffu, ls, off);
        bs += __shfl_down_sync(0xffffffffu, bs, off);
        c  += __shfl_down_sync(0xffffffffu, c, off);
    }
    __shared__ float wl[4], wb[4];
    __shared__ int wc_[4];
    const int w = threadIdx.x >> 5;
    if (lane == 0) { wl[w] = ls; wb[w] = bs; wc_[w] = c; }
    __syncthreads();
    if (threadIdx.x == 0) {
        g_fl[blockIdx.x] = wl[0] + wl[1] + wl[2] + wl[3];
        g_fb[blockIdx.x] = wb[0] + wb[1] + wb[2] + wb[3];
        g_fc[blockIdx.x] = wc_[0] + wc_[1] + wc_[2] + wc_[3];
    }
}

// ---------------- kernel D2: combine 32 partials -----------------------------
__global__ void final2_kernel(float* __restrict__ out) {
    const int lane = threadIdx.x;      // 32 threads
    float ls = g_fl[lane], bs = g_fb[lane];
    int c = g_fc[lane];
#pragma unroll
    for (int off = 16; off > 0; off >>= 1) {
        ls += __shfl_down_sync(0xffffffffu, ls, off);
        bs += __shfl_down_sync(0xffffffffu, bs, off);
        c  += __shfl_down_sync(0xffffffffu, c, off);
    }
    if (lane == 0) {
        const float bce = bs / (float)(N_ROWS * NCLS);
        out[0] = bce + ((c > 0) ? (ls / (float)c) : 0.f);
    }
}

// ---------------- launch ------------------------------------------------------
extern "C" void kernel_launch(void* const* d_in, const int* in_sizes, int n_in,
                              void* d_out, int out_size) {
    (void)in_sizes; (void)n_in; (void)out_size;
    const float* emb    = (const float*)d_in[0];
    const float* logits = (const float*)d_in[1];
    const int*   labels = (const int*)d_in[2];
    float* out = (float*)d_out;

    cudaFuncSetAttribute(sim_kernel, cudaFuncAttributeMaxDynamicSharedMemorySize, SMEM_TOTAL);

    convert_kernel<<<2048, 256>>>(emb);
    prep_kernel<<<N_ROWS, NCLS>>>(logits, labels);
    sim_kernel<<<NTRI, 256, SMEM_TOTAL>>>();
    final1_kernel<<<NT, 128>>>();
    final2_kernel<<<1, 32>>>(out);
}

// round 6
// speedup vs baseline: 5.9756x; 1.1861x over previous
#include <cuda_runtime.h>
#include <cuda_bf16.h>
#include <stdint.h>
#include <math.h>

#define N_ROWS 4096
#define DIMS   1024
#define NCLS   64
#define NT     32               // 4096/128 tiles per dim
#define NTRI   (NT * (NT + 1) / 2)   // 528 lower-triangular tiles
#define INV_T  14.285714285714286f

#define NCHUNK 48               // K=3072 in BK=64 chunks
#define STAGE_BYTES 32768       // A 16KB + B 16KB
#define SM_RMASK (2 * STAGE_BYTES)             // 65536
#define SM_CMASK (SM_RMASK + 1024)
#define SM_ROWP  (SM_CMASK + 1024)
#define SM_ROWS  (SM_ROWP + 512)
#define SM_COLP  (SM_ROWS + 512)
#define SM_COLS  (SM_COLP + 512)
#define SMEM_TOTAL (SM_COLS + 512)             // 69632 B -> 2 CTAs/SM

// ---------------- device scratch -------------------------------------------
__device__ __nv_bfloat16 g_hi[N_ROWS * DIMS];   // 8 MB
__device__ __nv_bfloat16 g_lo[N_ROWS * DIMS];   // 8 MB
__device__ unsigned long long g_mask[N_ROWS];
__device__ float g_w[N_ROWS];
__device__ float g_bce_part[N_ROWS];
__device__ float g_pp[NT * N_ROWS];
__device__ float g_ps[NT * N_ROWS];
__device__ float g_fl[NT], g_fb[NT];
__device__ int   g_fc[NT];

// ---------------- PTX helpers (baseline ISA only) ----------------------------
__device__ __forceinline__ uint32_t smem_u32(const void* p) {
    uint32_t a;
    asm("{ .reg .u64 t; cvta.to.shared.u64 t, %1; cvt.u32.u64 %0, t; }" : "=r"(a) : "l"(p));
    return a;
}
#define CP16(dst, src) \
    asm volatile("cp.async.cg.shared.global [%0], [%1], 16;" :: "r"(dst), "l"(src))
#define CP_COMMIT() asm volatile("cp.async.commit_group;")
#define CP_WAIT0()  asm volatile("cp.async.wait_group 0;")
#define LDSM4(r, a) \
    asm volatile("ldmatrix.sync.aligned.m8n8.x4.shared.b16 {%0,%1,%2,%3}, [%4];" \
        : "=r"((r)[0]), "=r"((r)[1]), "=r"((r)[2]), "=r"((r)[3]) : "r"(a))
#define MMA16816(c, a, b0, b1) \
    asm volatile("mma.sync.aligned.m16n8k16.row.col.f32.bf16.bf16.f32 " \
        "{%0,%1,%2,%3},{%4,%5,%6,%7},{%8,%9},{%0,%1,%2,%3};" \
        : "+f"((c)[0]), "+f"((c)[1]), "+f"((c)[2]), "+f"((c)[3]) \
        : "r"((a)[0]), "r"((a)[1]), "r"((a)[2]), "r"((a)[3]), "r"(b0), "r"(b1))

// ---------------- kernel A: fused convert (blocks 0..2047) + prep (2048..2559)
__global__ void fused_prep_kernel(const float* __restrict__ emb,
                                  const float* __restrict__ logits,
                                  const int* __restrict__ labels) {
    if (blockIdx.x < 2048) {
        // ---- convert: fp32 -> (hi, lo) bf16, row-major ----------------------
        const int idx = blockIdx.x * 256 + threadIdx.x;
        const float4* src = (const float4*)(emb + (size_t)idx * 8);
        const float4 x0 = src[0], x1 = src[1];
        const float v[8] = {x0.x, x0.y, x0.z, x0.w, x1.x, x1.y, x1.z, x1.w};
        uint32_t hw[4], lw[4];
#pragma unroll
        for (int i = 0; i < 4; i++) {
            const __nv_bfloat16 h0 = __float2bfloat16_rn(v[2*i]);
            const __nv_bfloat16 h1 = __float2bfloat16_rn(v[2*i+1]);
            const __nv_bfloat16 l0 = __float2bfloat16_rn(v[2*i]   - __bfloat162float(h0));
            const __nv_bfloat16 l1 = __float2bfloat16_rn(v[2*i+1] - __bfloat162float(h1));
            hw[i] = ((uint32_t)__bfloat16_as_ushort(h1) << 16) | __bfloat16_as_ushort(h0);
            lw[i] = ((uint32_t)__bfloat16_as_ushort(l1) << 16) | __bfloat16_as_ushort(l0);
        }
        ((uint4*)g_hi)[idx] = make_uint4(hw[0], hw[1], hw[2], hw[3]);
        ((uint4*)g_lo)[idx] = make_uint4(lw[0], lw[1], lw[2], lw[3]);
    } else {
        // ---- prep: 1 warp per row, 2 classes per lane -----------------------
        const int row = (blockIdx.x - 2048) * 8 + (threadIdx.x >> 5);
        const int lane = threadIdx.x & 31;
        const float2 xx = *(const float2*)(logits + row * NCLS + lane * 2);
        const int2 ll = *(const int2*)(labels + row * NCLS + lane * 2);
        float bce = 0.f, wn = 0.f, wd = 0.f;
        unsigned long long mk = 0ull;
        const float xv[2] = {xx.x, xx.y};
        const int lv[2] = {ll.x, ll.y};
#pragma unroll
        for (int q = 0; q < 2; q++) {
            const float x = xv[q];
            const float y = (float)lv[q];
            bce += fmaxf(x, 0.f) - x * y + log1pf(expf(-fabsf(x)));
            const float pr = 1.f / (1.f + expf(-x));
            const float ent = -(pr * logf(pr + 1e-8f) + (1.f - pr) * logf(1.f - pr + 1e-8f));
            wn += ent * y;
            wd += y;
            if (lv[q]) mk |= 1ull << (lane * 2 + q);
        }
#pragma unroll
        for (int off = 16; off > 0; off >>= 1) {
            bce += __shfl_xor_sync(0xffffffffu, bce, off);
            wn  += __shfl_xor_sync(0xffffffffu, wn, off);
            wd  += __shfl_xor_sync(0xffffffffu, wd, off);
            mk  |= __shfl_xor_sync(0xffffffffu, mk, off);
        }
        if (lane == 0) {
            g_bce_part[row] = bce;
            g_w[row] = wn / (wd + 1e-8f);
            g_mask[row] = mk;
        }
    }
}

// ---------------- kernel C: symmetric mma.sync GEMM + fused softmax sums ----
__global__ __launch_bounds__(256, 2)
void sim_kernel() {
    extern __shared__ char smem[];
    const uint32_t sbase = smem_u32(smem);
    const int tid = threadIdx.x;
    const int wid = tid >> 5, lane = tid & 31;
    const int wr = wid & 3, wc = wid >> 2;          // warp grid 4x2

    // map linear bid -> (I, J), J <= I
    const int bid = blockIdx.x;
    int I = (int)((sqrtf(8.f * (float)bid + 1.f) - 1.f) * 0.5f);
    while ((I + 1) * (I + 2) / 2 <= bid) I++;
    while (I * (I + 1) / 2 > bid) I--;
    const int J = bid - I * (I + 1) / 2;
    const bool isDiag = (I == J);
    const int rowBase = I * 128;
    const int colBase = J * 128;

    unsigned long long* rmaskS = (unsigned long long*)(smem + SM_RMASK);
    unsigned long long* cmaskS = (unsigned long long*)(smem + SM_CMASK);
    float* rowP = (float*)(smem + SM_ROWP);
    float* rowS = (float*)(smem + SM_ROWS);
    float* colP = (float*)(smem + SM_COLP);
    float* colS = (float*)(smem + SM_COLS);

    if (tid < 128) {
        rmaskS[tid] = g_mask[rowBase + tid];
        cmaskS[tid] = g_mask[colBase + tid];
        rowP[tid] = 0.f; rowS[tid] = 0.f;
        colP[tid] = 0.f; colS[tid] = 0.f;
    }

    // ---- cp.async fill mapping: 128-byte rows, XOR-8 swizzle ----------------
    const int r0 = tid >> 3;                 // rows 0..31, step 32 per pass
    const int g0 = tid & 7;                  // 16B group within 128B row
    const uint32_t dstOff = (uint32_t)(r0 * 128 + ((g0 ^ (r0 & 7)) * 16));
    const size_t gOffA = (size_t)(rowBase + r0) * DIMS + g0 * 8;
    const size_t gOffB = (size_t)(colBase + r0) * DIMS + g0 * 8;

    // ---- ldmatrix addressing -------------------------------------------------
    const int aRow = wr * 32 + (lane & 15);
    const uint32_t aR7 = (uint32_t)(aRow & 7);
    const int bRow = wc * 64 + (lane & 15);
    const uint32_t bR7 = (uint32_t)(bRow & 7);
    const uint32_t laneG = lane >> 4;

    float acc[2][8][4];
#pragma unroll
    for (int i = 0; i < 2; i++)
#pragma unroll
        for (int j = 0; j < 8; j++)
#pragma unroll
            for (int k = 0; k < 4; k++) acc[i][j][k] = 0.f;

    // prologue: fill stage 0 with chunk 0 (phase 0 -> hi/hi)
    {
        const uint32_t st = sbase;
#pragma unroll
        for (int i = 0; i < 4; i++) {
            CP16(st + dstOff + i * 4096,         g_hi + gOffA + (size_t)i * 32 * DIMS);
            CP16(st + 16384 + dstOff + i * 4096, g_hi + gOffB + (size_t)i * 32 * DIMS);
        }
        CP_COMMIT();
    }

    for (int c = 0; c < NCHUNK; c++) {
        CP_WAIT0();
        __syncthreads();
        // prefetch chunk c+1 into the other stage (consumed at iter c-1)
        if (c + 1 < NCHUNK) {
            const int cn = c + 1;
            const int p = cn >> 4;
            const size_t kk = (size_t)(cn & 15) * 64;
            const __nv_bfloat16* As = (p == 1) ? g_lo : g_hi;
            const __nv_bfloat16* Bs = (p == 2) ? g_lo : g_hi;
            const uint32_t st = sbase + (cn & 1) * STAGE_BYTES;
#pragma unroll
            for (int i = 0; i < 4; i++) {
                CP16(st + dstOff + i * 4096,         As + gOffA + kk + (size_t)i * 32 * DIMS);
                CP16(st + 16384 + dstOff + i * 4096, Bs + gOffB + kk + (size_t)i * 32 * DIMS);
            }
            CP_COMMIT();
        }

        const uint32_t st = sbase + (c & 1) * STAGE_BYTES;
#pragma unroll
        for (int ks = 0; ks < 4; ks++) {
            uint32_t a0[4], a1[4], b[4][4];
            const uint32_t gk = (uint32_t)(ks * 2) + laneG;
            LDSM4(a0, st + aRow * 128        + ((gk ^ aR7) * 16));
            LDSM4(a1, st + (aRow + 16) * 128 + ((gk ^ aR7) * 16));
#pragma unroll
            for (int n16 = 0; n16 < 4; n16++)
                LDSM4(b[n16], st + 16384 + (bRow + n16 * 16) * 128 + ((gk ^ bR7) * 16));
#pragma unroll
            for (int nt = 0; nt < 8; nt++) {
                const int n16 = nt >> 1, h = nt & 1;
                MMA16816(acc[0][nt], a0, b[n16][h], b[n16][h + 2]);
                MMA16816(acc[1][nt], a1, b[n16][h], b[n16][h + 2]);
            }
        }
    }

    // ---- fused epilogue ------------------------------------------------------
    const int g8 = lane >> 2;        // quad row 0..7
    const int cq = (lane & 3) * 2;   // quad col pair
    float cp[8][2], cs[8][2];
#pragma unroll
    for (int nt = 0; nt < 8; nt++) { cp[nt][0]=cp[nt][1]=cs[nt][0]=cs[nt][1]=0.f; }

#pragma unroll
    for (int mt = 0; mt < 2; mt++) {
#pragma unroll
        for (int h = 0; h < 2; h++) {
            const int rl = wr * 32 + mt * 16 + h * 8 + g8;
            const int gi = rowBase + rl;
            const unsigned long long rm = rmaskS[rl];
            float pa = 0.f, sa = 0.f;
#pragma unroll
            for (int nt = 0; nt < 8; nt++) {
#pragma unroll
                for (int j = 0; j < 2; j++) {
                    const int cl = wc * 64 + nt * 8 + cq + j;
                    if (!isDiag || colBase + cl != gi) {
                        const float e = __expf(acc[mt][nt][h * 2 + j] * INV_T);
                        const bool pos = (rm & cmaskS[cl]) != 0ull;
                        sa += e;
                        if (pos) pa += e;
                        cs[nt][j] += e;
                        if (pos) cp[nt][j] += e;
                    }
                }
            }
            pa += __shfl_xor_sync(0xffffffffu, pa, 1);
            pa += __shfl_xor_sync(0xffffffffu, pa, 2);
            sa += __shfl_xor_sync(0xffffffffu, sa, 1);
            sa += __shfl_xor_sync(0xffffffffu, sa, 2);
            if ((lane & 3) == 0) {
                atomicAdd(&rowP[rl], pa);
                atomicAdd(&rowS[rl], sa);
            }
        }
    }

    if (!isDiag) {
#pragma unroll
        for (int nt = 0; nt < 8; nt++) {
#pragma unroll
            for (int j = 0; j < 2; j++) {
                float p = cp[nt][j], s = cs[nt][j];
#pragma unroll
                for (int off = 4; off < 32; off <<= 1) {
                    p += __shfl_xor_sync(0xffffffffu, p, off);
                    s += __shfl_xor_sync(0xffffffffu, s, off);
                }
                if (g8 == 0) {
                    const int cl = wc * 64 + nt * 8 + cq + j;
                    atomicAdd(&colP[cl], p);
                    atomicAdd(&colS[cl], s);
                }
            }
        }
    }

    __syncthreads();
    if (tid < 128) {
        g_pp[J * N_ROWS + rowBase + tid] = rowP[tid];
        g_ps[J * N_ROWS + rowBase + tid] = rowS[tid];
        if (!isDiag) {
            g_pp[I * N_ROWS + colBase + tid] = colP[tid];
            g_ps[I * N_ROWS + colBase + tid] = colS[tid];
        }
    }
}

// ---------------- kernel D1: per-row loss, block partials --------------------
__global__ void final1_kernel() {
    const int row = blockIdx.x * 128 + threadIdx.x;
    float pp = 0.f, ss = 0.f;
#pragma unroll
    for (int sp = 0; sp < NT; sp++) {
        pp += g_pp[sp * N_ROWS + row];
        ss += g_ps[sp * N_ROWS + row];
    }
    float ls = 0.f;
    int c = 0;
    if (pp > 0.f) { ls = -logf(pp / (ss + 1e-8f)) * g_w[row]; c = 1; }
    float bs = g_bce_part[row];

    const int lane = threadIdx.x & 31;
#pragma unroll
    for (int off = 16; off > 0; off >>= 1) {
        ls += __shfl_down_sync(0xffffffffu, ls, off);
        bs += __shfl_down_sync(0xffffffffu, bs, off);
        c  += __shfl_down_sync(0xffffffffu, c, off);
    }
    __shared__ float wl[4], wb[4];
    __shared__ int wc_[4];
    const int w = threadIdx.x >> 5;
    if (lane == 0) { wl[w] = ls; wb[w] = bs; wc_[w] = c; }
    __syncthreads();
    if (threadIdx.x == 0) {
        g_fl[blockIdx.x] = wl[0] + wl[1] + wl[2] + wl[3];
        g_fb[blockIdx.x] = wb[0] + wb[1] + wb[2] + wb[3];
        g_fc[blockIdx.x] = wc_[0] + wc_[1] + wc_[2] + wc_[3];
    }
}

// ---------------- kernel D2: combine 32 partials -----------------------------
__global__ void final2_kernel(float* __restrict__ out) {
    const int lane = threadIdx.x;      // 32 threads
    float ls = g_fl[lane], bs = g_fb[lane];
    int c = g_fc[lane];
#pragma unroll
    for (int off = 16; off > 0; off >>= 1) {
        ls += __shfl_down_sync(0xffffffffu, ls, off);
        bs += __shfl_down_sync(0xffffffffu, bs, off);
        c  += __shfl_down_sync(0xffffffffu, c, off);
    }
    if (lane == 0) {
        const float bce = bs / (float)(N_ROWS * NCLS);
        out[0] = bce + ((c > 0) ? (ls / (float)c) : 0.f);
    }
}

// ---------------- launch ------------------------------------------------------
extern "C" void kernel_launch(void* const* d_in, const int* in_sizes, int n_in,
                              void* d_out, int out_size) {
    (void)in_sizes; (void)n_in; (void)out_size;
    const float* emb    = (const float*)d_in[0];
    const float* logits = (const float*)d_in[1];
    const int*   labels = (const int*)d_in[2];
    float* out = (float*)d_out;

    cudaFuncSetAttribute(sim_kernel, cudaFuncAttributeMaxDynamicSharedMemorySize, SMEM_TOTAL);

    fused_prep_kernel<<<2560, 256>>>(emb, logits, labels);
    sim_kernel<<<NTRI, 256, SMEM_TOTAL>>>();
    final1_kernel<<<NT, 128>>>();
    final2_kernel<<<1, 32>>>(out);
}

// round 7
// speedup vs baseline: 13.9767x; 2.3390x over previous
#include <cuda_runtime.h>
#include <cuda_fp16.h>
#include <stdint.h>
#include <math.h>

#define N_ROWS 4096
#define DIMS   1024
#define NCLS   64
#define NT     32               // 4096/128 tiles per dim
#define NTRI   (NT * (NT + 1) / 2)   // 528 lower-triangular tiles
#define INV_T  14.285714285714286f

#define NCHUNK 16               // K=1024 in BK=64 chunks
#define STAGE_BYTES 32768       // A 16KB + B 16KB
#define SM_RMASK (2 * STAGE_BYTES)             // 65536
#define SM_CMASK (SM_RMASK + 1024)
#define SM_ROWP  (SM_CMASK + 1024)
#define SM_ROWS  (SM_ROWP + 512)
#define SM_COLP  (SM_ROWS + 512)
#define SM_COLS  (SM_COLP + 512)
#define SMEM_TOTAL (SM_COLS + 512)             // 69632 B -> 2 CTAs/SM

// ---------------- device scratch -------------------------------------------
__device__ __half g_h[N_ROWS * DIMS];           // 8 MB fp16 embeddings
__device__ unsigned long long g_mask[N_ROWS];
__device__ float g_w[N_ROWS];
__device__ float g_bce_part[N_ROWS];
__device__ float g_pp[NT * N_ROWS];
__device__ float g_ps[NT * N_ROWS];
__device__ float g_fl[NT], g_fb[NT];
__device__ int   g_fc[NT];

// ---------------- PTX helpers (baseline ISA only) ----------------------------
__device__ __forceinline__ uint32_t smem_u32(const void* p) {
    uint32_t a;
    asm("{ .reg .u64 t; cvta.to.shared.u64 t, %1; cvt.u32.u64 %0, t; }" : "=r"(a) : "l"(p));
    return a;
}
#define CP16(dst, src) \
    asm volatile("cp.async.cg.shared.global [%0], [%1], 16;" :: "r"(dst), "l"(src))
#define CP_COMMIT() asm volatile("cp.async.commit_group;")
#define CP_WAIT0()  asm volatile("cp.async.wait_group 0;")
#define LDSM4(r, a) \
    asm volatile("ldmatrix.sync.aligned.m8n8.x4.shared.b16 {%0,%1,%2,%3}, [%4];" \
        : "=r"((r)[0]), "=r"((r)[1]), "=r"((r)[2]), "=r"((r)[3]) : "r"(a))
#define MMA16816(c, a, b0, b1) \
    asm volatile("mma.sync.aligned.m16n8k16.row.col.f32.f16.f16.f32 " \
        "{%0,%1,%2,%3},{%4,%5,%6,%7},{%8,%9},{%0,%1,%2,%3};" \
        : "+f"((c)[0]), "+f"((c)[1]), "+f"((c)[2]), "+f"((c)[3]) \
        : "r"((a)[0]), "r"((a)[1]), "r"((a)[2]), "r"((a)[3]), "r"(b0), "r"(b1))

// ---------------- kernel A: fused convert (blocks 0..2047) + prep (2048..2559)
__global__ void fused_prep_kernel(const float* __restrict__ emb,
                                  const float* __restrict__ logits,
                                  const int* __restrict__ labels) {
    if (blockIdx.x < 2048) {
        // ---- convert: fp32 -> fp16, row-major -------------------------------
        const int idx = blockIdx.x * 256 + threadIdx.x;     // 8 elems per thread
        const float4* src = (const float4*)(emb + (size_t)idx * 8);
        const float4 x0 = src[0], x1 = src[1];
        const float v[8] = {x0.x, x0.y, x0.z, x0.w, x1.x, x1.y, x1.z, x1.w};
        uint32_t hw[4];
#pragma unroll
        for (int i = 0; i < 4; i++) {
            const __half h0 = __float2half_rn(v[2*i]);
            const __half h1 = __float2half_rn(v[2*i+1]);
            hw[i] = ((uint32_t)__half_as_ushort(h1) << 16) | __half_as_ushort(h0);
        }
        ((uint4*)g_h)[idx] = make_uint4(hw[0], hw[1], hw[2], hw[3]);
    } else {
        // ---- prep: 1 warp per row, 2 classes per lane -----------------------
        const int row = (blockIdx.x - 2048) * 8 + (threadIdx.x >> 5);
        const int lane = threadIdx.x & 31;
        const float2 xx = *(const float2*)(logits + row * NCLS + lane * 2);
        const int2 ll = *(const int2*)(labels + row * NCLS + lane * 2);
        float bce = 0.f, wn = 0.f, wd = 0.f;
        unsigned long long mk = 0ull;
        const float xv[2] = {xx.x, xx.y};
        const int lv[2] = {ll.x, ll.y};
#pragma unroll
        for (int q = 0; q < 2; q++) {
            const float x = xv[q];
            const float y = (float)lv[q];
            bce += fmaxf(x, 0.f) - x * y + log1pf(expf(-fabsf(x)));
            const float pr = 1.f / (1.f + expf(-x));
            const float ent = -(pr * logf(pr + 1e-8f) + (1.f - pr) * logf(1.f - pr + 1e-8f));
            wn += ent * y;
            wd += y;
            if (lv[q]) mk |= 1ull << (lane * 2 + q);
        }
#pragma unroll
        for (int off = 16; off > 0; off >>= 1) {
            bce += __shfl_xor_sync(0xffffffffu, bce, off);
            wn  += __shfl_xor_sync(0xffffffffu, wn, off);
            wd  += __shfl_xor_sync(0xffffffffu, wd, off);
            mk  |= __shfl_xor_sync(0xffffffffu, mk, off);
        }
        if (lane == 0) {
            g_bce_part[row] = bce;
            g_w[row] = wn / (wd + 1e-8f);
            g_mask[row] = mk;
        }
    }
}

// ---------------- kernel C: symmetric fp16 mma.sync GEMM + fused softmax ----
__global__ __launch_bounds__(256, 2)
void sim_kernel() {
    extern __shared__ char smem[];
    const uint32_t sbase = smem_u32(smem);
    const int tid = threadIdx.x;
    const int wid = tid >> 5, lane = tid & 31;
    const int wr = wid & 3, wc = wid >> 2;          // warp grid 4x2

    // map linear bid -> (I, J), J <= I
    const int bid = blockIdx.x;
    int I = (int)((sqrtf(8.f * (float)bid + 1.f) - 1.f) * 0.5f);
    while ((I + 1) * (I + 2) / 2 <= bid) I++;
    while (I * (I + 1) / 2 > bid) I--;
    const int J = bid - I * (I + 1) / 2;
    const bool isDiag = (I == J);
    const int rowBase = I * 128;
    const int colBase = J * 128;

    unsigned long long* rmaskS = (unsigned long long*)(smem + SM_RMASK);
    unsigned long long* cmaskS = (unsigned long long*)(smem + SM_CMASK);
    float* rowP = (float*)(smem + SM_ROWP);
    float* rowS = (float*)(smem + SM_ROWS);
    float* colP = (float*)(smem + SM_COLP);
    float* colS = (float*)(smem + SM_COLS);

    if (tid < 128) {
        rmaskS[tid] = g_mask[rowBase + tid];
        cmaskS[tid] = g_mask[colBase + tid];
        rowP[tid] = 0.f; rowS[tid] = 0.f;
        colP[tid] = 0.f; colS[tid] = 0.f;
    }

    // ---- cp.async fill mapping: 128-byte rows, XOR-8 swizzle ----------------
    const int r0 = tid >> 3;                 // rows 0..31, step 32 per pass
    const int g0 = tid & 7;                  // 16B group within 128B row
    const uint32_t dstOff = (uint32_t)(r0 * 128 + ((g0 ^ (r0 & 7)) * 16));
    const size_t gOffA = (size_t)(rowBase + r0) * DIMS + g0 * 8;
    const size_t gOffB = (size_t)(colBase + r0) * DIMS + g0 * 8;

    // ---- ldmatrix addressing -------------------------------------------------
    const int aRow = wr * 32 + (lane & 15);
    const uint32_t aR7 = (uint32_t)(aRow & 7);
    const int bRow = wc * 64 + (lane & 15);
    const uint32_t bR7 = (uint32_t)(bRow & 7);
    const uint32_t laneG = lane >> 4;

    float acc[2][8][4];
#pragma unroll
    for (int i = 0; i < 2; i++)
#pragma unroll
        for (int j = 0; j < 8; j++)
#pragma unroll
            for (int k = 0; k < 4; k++) acc[i][j][k] = 0.f;

    // prologue: fill stage 0 with chunk 0
    {
        const uint32_t st = sbase;
#pragma unroll
        for (int i = 0; i < 4; i++) {
            CP16(st + dstOff + i * 4096,         g_h + gOffA + (size_t)i * 32 * DIMS);
            CP16(st + 16384 + dstOff + i * 4096, g_h + gOffB + (size_t)i * 32 * DIMS);
        }
        CP_COMMIT();
    }

    for (int c = 0; c < NCHUNK; c++) {
        CP_WAIT0();
        __syncthreads();
        // prefetch chunk c+1 into the other stage (consumed at iter c-1)
        if (c + 1 < NCHUNK) {
            const size_t kk = (size_t)(c + 1) * 64;
            const uint32_t st = sbase + ((c + 1) & 1) * STAGE_BYTES;
#pragma unroll
            for (int i = 0; i < 4; i++) {
                CP16(st + dstOff + i * 4096,         g_h + gOffA + kk + (size_t)i * 32 * DIMS);
                CP16(st + 16384 + dstOff + i * 4096, g_h + gOffB + kk + (size_t)i * 32 * DIMS);
            }
            CP_COMMIT();
        }

        const uint32_t st = sbase + (c & 1) * STAGE_BYTES;
#pragma unroll
        for (int ks = 0; ks < 4; ks++) {
            uint32_t a0[4], a1[4], b[4][4];
            const uint32_t gk = (uint32_t)(ks * 2) + laneG;
            LDSM4(a0, st + aRow * 128        + ((gk ^ aR7) * 16));
            LDSM4(a1, st + (aRow + 16) * 128 + ((gk ^ aR7) * 16));
#pragma unroll
            for (int n16 = 0; n16 < 4; n16++)
                LDSM4(b[n16], st + 16384 + (bRow + n16 * 16) * 128 + ((gk ^ bR7) * 16));
#pragma unroll
            for (int nt = 0; nt < 8; nt++) {
                const int n16 = nt >> 1, h = nt & 1;
                MMA16816(acc[0][nt], a0, b[n16][h], b[n16][h + 2]);
                MMA16816(acc[1][nt], a1, b[n16][h], b[n16][h + 2]);
            }
        }
    }

    // ---- fused epilogue ------------------------------------------------------
    const int g8 = lane >> 2;        // quad row 0..7
    const int cq = (lane & 3) * 2;   // quad col pair
    float cp[8][2], cs[8][2];
#pragma unroll
    for (int nt = 0; nt < 8; nt++) { cp[nt][0]=cp[nt][1]=cs[nt][0]=cs[nt][1]=0.f; }

#pragma unroll
    for (int mt = 0; mt < 2; mt++) {
#pragma unroll
        for (int h = 0; h < 2; h++) {
            const int rl = wr * 32 + mt * 16 + h * 8 + g8;
            const int gi = rowBase + rl;
            const unsigned long long rm = rmaskS[rl];
            float pa = 0.f, sa = 0.f;
#pragma unroll
            for (int nt = 0; nt < 8; nt++) {
#pragma unroll
                for (int j = 0; j < 2; j++) {
                    const int cl = wc * 64 + nt * 8 + cq + j;
                    if (!isDiag || colBase + cl != gi) {
                        const float e = __expf(acc[mt][nt][h * 2 + j] * INV_T);
                        const bool pos = (rm & cmaskS[cl]) != 0ull;
                        sa += e;
                        if (pos) pa += e;
                        cs[nt][j] += e;
                        if (pos) cp[nt][j] += e;
                    }
                }
            }
            pa += __shfl_xor_sync(0xffffffffu, pa, 1);
            pa += __shfl_xor_sync(0xffffffffu, pa, 2);
            sa += __shfl_xor_sync(0xffffffffu, sa, 1);
            sa += __shfl_xor_sync(0xffffffffu, sa, 2);
            if ((lane & 3) == 0) {
                atomicAdd(&rowP[rl], pa);
                atomicAdd(&rowS[rl], sa);
            }
        }
    }

    if (!isDiag) {
#pragma unroll
        for (int nt = 0; nt < 8; nt++) {
#pragma unroll
            for (int j = 0; j < 2; j++) {
                float p = cp[nt][j], s = cs[nt][j];
#pragma unroll
                for (int off = 4; off < 32; off <<= 1) {
                    p += __shfl_xor_sync(0xffffffffu, p, off);
                    s += __shfl_xor_sync(0xffffffffu, s, off);
                }
                if (g8 == 0) {
                    const int cl = wc * 64 + nt * 8 + cq + j;
                    atomicAdd(&colP[cl], p);
                    atomicAdd(&colS[cl], s);
                }
            }
        }
    }

    __syncthreads();
    if (tid < 128) {
        g_pp[J * N_ROWS + rowBase + tid] = rowP[tid];
        g_ps[J * N_ROWS + rowBase + tid] = rowS[tid];
        if (!isDiag) {
            g_pp[I * N_ROWS + colBase + tid] = colP[tid];
            g_ps[I * N_ROWS + colBase + tid] = colS[tid];
        }
    }
}

// ---------------- kernel D1: per-row loss, block partials --------------------
__global__ void final1_kernel() {
    const int row = blockIdx.x * 128 + threadIdx.x;
    float pp = 0.f, ss = 0.f;
#pragma unroll
    for (int sp = 0; sp < NT; sp++) {
        pp += g_pp[sp * N_ROWS + row];
        ss += g_ps[sp * N_ROWS + row];
    }
    float ls = 0.f;
    int c = 0;
    if (pp > 0.f) { ls = -logf(pp / (ss + 1e-8f)) * g_w[row]; c = 1; }
    float bs = g_bce_part[row];

    const int lane = threadIdx.x & 31;
#pragma unroll
    for (int off = 16; off > 0; off >>= 1) {
        ls += __shfl_down_sync(0xffffffffu, ls, off);
        bs += __shfl_down_sync(0xffffffffu, bs, off);
        c  += __shfl_down_sync(0xffffffffu, c, off);
    }
    __shared__ float wl[4], wb[4];
    __shared__ int wc_[4];
    const int w = threadIdx.x >> 5;
    if (lane == 0) { wl[w] = ls; wb[w] = bs; wc_[w] = c; }
    __syncthreads();
    if (threadIdx.x == 0) {
        g_fl[blockIdx.x] = wl[0] + wl[1] + wl[2] + wl[3];
        g_fb[blockIdx.x] = wb[0] + wb[1] + wb[2] + wb[3];
        g_fc[blockIdx.x] = wc_[0] + wc_[1] + wc_[2] + wc_[3];
    }
}

// ---------------- kernel D2: combine 32 partials -----------------------------
__global__ void final2_kernel(float* __restrict__ out) {
    const int lane = threadIdx.x;      // 32 threads
    float ls = g_fl[lane], bs = g_fb[lane];
    int c = g_fc[lane];
#pragma unroll
    for (int off = 16; off > 0; off >>= 1) {
        ls += __shfl_down_sync(0xffffffffu, ls, off);
        bs += __shfl_down_sync(0xffffffffu, bs, off);
        c  += __shfl_down_sync(0xffffffffu, c, off);
    }
    if (lane == 0) {
        const float bce = bs / (float)(N_ROWS * NCLS);
        out[0] = bce + ((c > 0) ? (ls / (float)c) : 0.f);
    }
}

// ---------------- launch ------------------------------------------------------
extern "C" void kernel_launch(void* const* d_in, const int* in_sizes, int n_in,
                              void* d_out, int out_size) {
    (void)in_sizes; (void)n_in; (void)out_size;
    const float* emb    = (const float*)d_in[0];
    const float* logits = (const float*)d_in[1];
    const int*   labels = (const int*)d_in[2];
    float* out = (float*)d_out;

    cudaFuncSetAttribute(sim_kernel, cudaFuncAttributeMaxDynamicSharedMemorySize, SMEM_TOTAL);

    fused_prep_kernel<<<2560, 256>>>(emb, logits, labels);
    sim_kernel<<<NTRI, 256, SMEM_TOTAL>>>();
    final1_kernel<<<NT, 128>>>();
    final2_kernel<<<1, 32>>>(out);
}